// round 3
// baseline (speedup 1.0000x reference)
#include <cuda_runtime.h>
#include <math.h>

// Problem constants (fixed shapes per reference)
constexpr int Bb  = 2;
constexpr int S   = 2048;
constexpr int E   = 1024;
constexpr int NH  = 16;
constexpr int DH  = 64;
constexpr int E3  = 3 * E;
constexpr int MROWS = Bb * S;   // 4096

// Scratch (device globals — allocation-free per harness rules)
__device__ float g_qkv[(size_t)MROWS * E3];  // [b*s, 3E] row-major
__device__ float g_att[(size_t)MROWS * E];   // [b*s, E] merged-head attention output

// ---------------------------------------------------------------------------
// SGEMM: C[M,N] = A[M,K] @ B[K,N] + bias[N]
// 128x128 block tile, BK=8, 256 threads, 8x8 register tile per thread.
// mode: 1 -> C is g_qkv (ignore C_), 2 -> A is g_att (ignore A_), 0 -> use params
// ---------------------------------------------------------------------------
constexpr int BM = 128, BN = 128, BKg = 8;

__global__ __launch_bounds__(256) void sgemm_bias_kernel(
    const float* __restrict__ A_, const float* __restrict__ Bm,
    const float* __restrict__ bias, float* __restrict__ C_,
    int M, int N, int K, int mode)
{
    __shared__ float As[BKg][BM + 4];   // transposed A tile, padded
    __shared__ float Bs[BKg][BN];

    const float* A = (mode == 2) ? g_att : A_;
    float*       C = (mode == 1) ? g_qkv : C_;

    const int tid = threadIdx.x;
    const int tr  = tid >> 4;   // 0..15
    const int tc  = tid & 15;   // 0..15

    const int rowBase = blockIdx.y * BM;
    const int colBase = blockIdx.x * BN;

    // global->smem load mapping
    const int aRow = tid >> 1;          // 0..127
    const int aCol = (tid & 1) << 2;    // 0 or 4
    const int bRow = tid >> 5;          // 0..7
    const int bCol = (tid & 31) << 2;   // 0..124

    const float* Ap = A + (size_t)(rowBase + aRow) * K + aCol;
    const float* Bp = Bm + (size_t)bRow * N + colBase + bCol;

    float acc[8][8];
#pragma unroll
    for (int i = 0; i < 8; i++)
#pragma unroll
        for (int j = 0; j < 8; j++) acc[i][j] = 0.f;

    for (int k0 = 0; k0 < K; k0 += BKg) {
        float4 av = *(const float4*)Ap;
        float4 bv = *(const float4*)Bp;
        Ap += BKg;
        Bp += (size_t)BKg * N;

        As[aCol + 0][aRow] = av.x;
        As[aCol + 1][aRow] = av.y;
        As[aCol + 2][aRow] = av.z;
        As[aCol + 3][aRow] = av.w;
        *(float4*)&Bs[bRow][bCol] = bv;
        __syncthreads();

#pragma unroll
        for (int kk = 0; kk < BKg; kk++) {
            float ra[8], rb[8];
            *(float4*)&ra[0] = *(const float4*)&As[kk][tr * 8];
            *(float4*)&ra[4] = *(const float4*)&As[kk][tr * 8 + 4];
            *(float4*)&rb[0] = *(const float4*)&Bs[kk][tc * 8];
            *(float4*)&rb[4] = *(const float4*)&Bs[kk][tc * 8 + 4];
#pragma unroll
            for (int i = 0; i < 8; i++)
#pragma unroll
                for (int j = 0; j < 8; j++)
                    acc[i][j] = fmaf(ra[i], rb[j], acc[i][j]);
        }
        __syncthreads();
    }

    // epilogue: add bias, vectorized store
    float bvv[8];
    *(float4*)&bvv[0] = *(const float4*)&bias[colBase + tc * 8];
    *(float4*)&bvv[4] = *(const float4*)&bias[colBase + tc * 8 + 4];
#pragma unroll
    for (int i = 0; i < 8; i++) {
        float outv[8];
#pragma unroll
        for (int j = 0; j < 8; j++) outv[j] = acc[i][j] + bvv[j];
        float* cp = C + (size_t)(rowBase + tr * 8 + i) * N + colBase + tc * 8;
        *(float4*)cp       = *(float4*)&outv[0];
        *(float4*)(cp + 4) = *(float4*)&outv[4];
    }
}

// ---------------------------------------------------------------------------
// Causal flash attention, fp32.
// One block per (q-tile of 64 rows, head, batch). 256 threads (16x16 grid).
// K processed in tiles of 32 rows. Online softmax. Reads g_qkv, writes g_att.
// Thread (tr,tc): S rows i = tr+16r (r<4), S cols j = tc+16c (c<2),
//                 O rows i = tr+16r,      O cols d = 4*tc..4*tc+3.
// ---------------------------------------------------------------------------
constexpr int BQ  = 64;
constexpr int BKt = 32;
constexpr int KST = 68;   // padded K/V row stride (floats)
constexpr int PST = 36;   // padded P row stride

__global__ __launch_bounds__(256) void attn_kernel()
{
    __shared__ float Qs[BQ][64];      // 16384 B
    __shared__ float Ks[BKt][KST];    //  8704 B
    __shared__ float Vs[BKt][KST];    //  8704 B
    __shared__ float Ps[BQ][PST];     //  9216 B   (total 43008 < 48K)

    const int tid = threadIdx.x;
    const int tr  = tid >> 4;
    const int tc  = tid & 15;

    const int qt = blockIdx.x;
    const int h  = blockIdx.y;
    const int b  = blockIdx.z;
    const int qs = qt * BQ;

    const float* qbase = g_qkv + (size_t)b * S * E3 + (size_t)h * DH;
    const float* kbase = qbase + E;
    const float* vbase = qbase + 2 * E;

    // load Q tile [64 x 64]
    {
        const int lr = tid >> 2;            // 0..63
        const int lc = (tid & 3) << 4;      // 0,16,32,48
        const float* src = qbase + (size_t)(qs + lr) * E3 + lc;
#pragma unroll
        for (int u = 0; u < 4; u++)
            *(float4*)&Qs[lr][lc + 4 * u] = *(const float4*)(src + 4 * u);
    }

    float m[4], l[4], o[4][4];
#pragma unroll
    for (int r = 0; r < 4; r++) {
        m[r] = -1e30f; l[r] = 0.f;
#pragma unroll
        for (int c = 0; c < 4; c++) o[r][c] = 0.f;
    }

    const int ktiles = 2 * qt + 2;      // causal: ks <= qs+63
    const int klr = tid >> 3;           // 0..31
    const int klc = (tid & 7) << 3;     // 0..56

    for (int kt = 0; kt < ktiles; kt++) {
        const int ks = kt * BKt;
        // load K, V tiles [32 x 64]
        {
            const float* ksrc = kbase + (size_t)(ks + klr) * E3 + klc;
            const float* vsrc = vbase + (size_t)(ks + klr) * E3 + klc;
            *(float4*)&Ks[klr][klc]     = *(const float4*)(ksrc);
            *(float4*)&Ks[klr][klc + 4] = *(const float4*)(ksrc + 4);
            *(float4*)&Vs[klr][klc]     = *(const float4*)(vsrc);
            *(float4*)&Vs[klr][klc + 4] = *(const float4*)(vsrc + 4);
        }
        __syncthreads();

        // S = Q K^T  (4x2 per thread)
        float sv[4][2];
#pragma unroll
        for (int r = 0; r < 4; r++) { sv[r][0] = 0.f; sv[r][1] = 0.f; }
#pragma unroll
        for (int d0 = 0; d0 < 64; d0 += 4) {
            float4 kv0 = *(const float4*)&Ks[tc][d0];
            float4 kv1 = *(const float4*)&Ks[tc + 16][d0];
#pragma unroll
            for (int r = 0; r < 4; r++) {
                float4 qv = *(const float4*)&Qs[tr + 16 * r][d0];
                sv[r][0] += qv.x * kv0.x + qv.y * kv0.y + qv.z * kv0.z + qv.w * kv0.w;
                sv[r][1] += qv.x * kv1.x + qv.y * kv1.y + qv.z * kv1.z + qv.w * kv1.w;
            }
        }

        // scale + causal mask
#pragma unroll
        for (int r = 0; r < 4; r++)
#pragma unroll
            for (int c = 0; c < 2; c++) {
                const int qi = qs + tr + 16 * r;
                const int kj = ks + tc + 16 * c;
                const float x = sv[r][c] * 0.125f;     // 1/sqrt(64)
                sv[r][c] = (kj <= qi) ? x : -1e30f;
            }

        // row max across tc (lane bits 0..3)
        float rm[4];
#pragma unroll
        for (int r = 0; r < 4; r++) rm[r] = fmaxf(sv[r][0], sv[r][1]);
#pragma unroll
        for (int off = 1; off < 16; off <<= 1)
#pragma unroll
            for (int r = 0; r < 4; r++)
                rm[r] = fmaxf(rm[r], __shfl_xor_sync(0xffffffffu, rm[r], off));

        float alpha[4], rs[4];
#pragma unroll
        for (int r = 0; r < 4; r++) {
            const float mn = fmaxf(m[r], rm[r]);
            alpha[r] = __expf(m[r] - mn);
            m[r] = mn;
            sv[r][0] = __expf(sv[r][0] - mn);
            sv[r][1] = __expf(sv[r][1] - mn);
            rs[r] = sv[r][0] + sv[r][1];
        }
#pragma unroll
        for (int off = 1; off < 16; off <<= 1)
#pragma unroll
            for (int r = 0; r < 4; r++)
                rs[r] += __shfl_xor_sync(0xffffffffu, rs[r], off);
#pragma unroll
        for (int r = 0; r < 4; r++) {
            l[r] = l[r] * alpha[r] + rs[r];
#pragma unroll
            for (int c = 0; c < 4; c++) o[r][c] *= alpha[r];
        }

        // stage P
#pragma unroll
        for (int r = 0; r < 4; r++) {
            Ps[tr + 16 * r][tc]      = sv[r][0];
            Ps[tr + 16 * r][tc + 16] = sv[r][1];
        }
        __syncthreads();

        // O += P @ V
#pragma unroll
        for (int j0 = 0; j0 < BKt; j0 += 4) {
            float4 vv[4];
#pragma unroll
            for (int jj = 0; jj < 4; jj++)
                vv[jj] = *(const float4*)&Vs[j0 + jj][tc * 4];
#pragma unroll
            for (int r = 0; r < 4; r++) {
                float4 pv = *(const float4*)&Ps[tr + 16 * r][j0];
                o[r][0] += pv.x * vv[0].x + pv.y * vv[1].x + pv.z * vv[2].x + pv.w * vv[3].x;
                o[r][1] += pv.x * vv[0].y + pv.y * vv[1].y + pv.z * vv[2].y + pv.w * vv[3].y;
                o[r][2] += pv.x * vv[0].z + pv.y * vv[1].z + pv.z * vv[2].z + pv.w * vv[3].z;
                o[r][3] += pv.x * vv[0].w + pv.y * vv[1].w + pv.z * vv[2].w + pv.w * vv[3].w;
            }
        }
        __syncthreads();
    }

    // finalize: divide by l, write merged-head layout [b*s, E]
#pragma unroll
    for (int r = 0; r < 4; r++) {
        const float inv = 1.0f / l[r];
        float4 ov;
        ov.x = o[r][0] * inv;
        ov.y = o[r][1] * inv;
        ov.z = o[r][2] * inv;
        ov.w = o[r][3] * inv;
        float* dst = g_att + (size_t)(b * S + qs + tr + 16 * r) * E + h * DH + tc * 4;
        *(float4*)dst = ov;
    }
}

// ---------------------------------------------------------------------------
// Launch: QKV GEMM -> attention -> proj GEMM (all graph-capturable)
// ---------------------------------------------------------------------------
extern "C" void kernel_launch(void* const* d_in, const int* in_sizes, int n_in,
                              void* d_out, int out_size)
{
    const float* hs     = (const float*)d_in[0];
    const float* w_attn = (const float*)d_in[1];
    const float* b_attn = (const float*)d_in[2];
    const float* w_proj = (const float*)d_in[3];
    const float* b_proj = (const float*)d_in[4];
    float* out = (float*)d_out;

    dim3 blk(256);

    // QKV: [4096,1024] @ [1024,3072] + b -> g_qkv
    dim3 g1(E3 / BN, MROWS / BM);   // 24 x 32
    sgemm_bias_kernel<<<g1, blk>>>(hs, w_attn, b_attn, nullptr,
                                   MROWS, E3, E, /*mode=*/1);

    // causal attention over g_qkv -> g_att
    dim3 g2(S / BQ, NH, Bb);        // 32 x 16 x 2
    attn_kernel<<<g2, blk>>>();

    // proj: g_att @ [1024,1024] + b -> out
    dim3 g3(E / BN, MROWS / BM);    // 8 x 32
    sgemm_bias_kernel<<<g3, blk>>>(nullptr, w_proj, b_proj, out,
                                   MROWS, E, E, /*mode=*/2);
}